// round 15
// baseline (speedup 1.0000x reference)
#include <cuda_runtime.h>
#include <cuda_fp16.h>
#include <cstdint>

// Problem constants
#define D       256
#define BATCH   1024
#define TSTEPS  1024
#define CHUNK   128
#define MAT     (D * D)
#define NCTA    296                // 2 CTAs/SM x 148 SMs (fully resident)
#define NJOBS   2048               // fill jobs: 16 zgroups x 128 tiles
#define TICKS_PER_RUN (NJOBS + NCTA)

// ---------------------------------------------------------------------------
// Static device scratch
// ---------------------------------------------------------------------------
__device__ float g_A [MAT];                   // A = kernel * DT
__device__ float g_T1[MAT];                   // D2, later P512
__device__ float g_T2[MAT];                   // D1, later P256
__device__ float g_X [4 * MAT];               // A2/E^896, E^384, E^640, E^768
__device__ float g_P [(CHUNK + 1) * MAT];     // P[i] = E^i fp32, i=1..128
__device__ unsigned g_bar;                    // monotonic barrier counter (never reset)
__device__ unsigned g_tick;                   // monotonic ticket counter (never reset)
// fp16 operands, pre-tiled + pre-swizzled (XOR-8 on 16B groups) for ldmatrix:
__device__ uint4 g_PB[128 * 4 * 2048];        // B^T tiles (hi only), 16 MB
__device__ uint4 g_ZH[64 * 4 * 1024];         // A tiles (hi only), 4 MB

// ---------------------------------------------------------------------------
// Helpers
// ---------------------------------------------------------------------------
__device__ __forceinline__ uint32_t smem_u32(const void* p) {
    uint32_t a;
    asm("{ .reg .u64 t; cvta.to.shared.u64 t, %1; cvt.u32.u64 %0, t; }"
        : "=r"(a) : "l"(p));
    return a;
}
__device__ __forceinline__ void fma2(unsigned long long& d,
                                     unsigned long long a,
                                     unsigned long long b) {
    asm("fma.rn.f32x2 %0, %1, %2, %0;" : "+l"(d) : "l"(a), "l"(b));
}
__device__ __forceinline__ unsigned long long dup2(float x) {
    unsigned long long r;
    asm("mov.b64 %0, {%1, %1};" : "=l"(r) : "f"(x));
    return r;
}
__device__ __forceinline__ void ldsm4(uint32_t* r, uint32_t addr) {
    asm volatile("ldmatrix.sync.aligned.m8n8.x4.shared.b16 {%0,%1,%2,%3}, [%4];"
                 : "=r"(r[0]), "=r"(r[1]), "=r"(r[2]), "=r"(r[3]) : "r"(addr));
}
__device__ __forceinline__ void mma16816h(float* d, const uint32_t* a,
                                          uint32_t b0, uint32_t b1) {
    asm volatile(
        "mma.sync.aligned.m16n8k16.row.col.f32.f16.f16.f32 "
        "{%0,%1,%2,%3}, {%4,%5,%6,%7}, {%8,%9}, {%0,%1,%2,%3};"
        : "+f"(d[0]), "+f"(d[1]), "+f"(d[2]), "+f"(d[3])
        : "r"(a[0]), "r"(a[1]), "r"(a[2]), "r"(a[3]), "r"(b0), "r"(b1));
}
#define CP16(dst, src) \
    asm volatile("cp.async.cg.shared.global [%0], [%1], 16;" \
                 :: "r"(dst), "l"(src))
#define CP_COMMIT() asm volatile("cp.async.commit_group;" ::: "memory")
#define CP_WAIT1()  asm volatile("cp.async.wait_group 1;" ::: "memory")
#define CP_WAIT0()  asm volatile("cp.async.wait_group 0;" ::: "memory")
#define BARH(id)    asm volatile("bar.sync %0, 128;" :: "r"(id) : "memory")

__device__ __forceinline__ uint32_t packh2(__half a, __half b) {
    __half_raw ar = *(__half_raw*)&a, br = *(__half_raw*)&b;
    return (uint32_t)ar.x | ((uint32_t)br.x << 16);
}

// Global barrier; reset-free. Each run adds exactly NBARS*NCTA arrivals, so
// run base == 0 (mod NCTA); first arrival's OLD value recovers it.
__device__ __forceinline__ void gbar(unsigned& rb, int& k) {
    __syncthreads();
    if (threadIdx.x == 0) {
        __threadfence();
        unsigned old = atomicAdd(&g_bar, 1u);
        if (k == 0) rb = old - (old % (unsigned)NCTA);
        ++k;
        unsigned need = (unsigned)k * NCTA;
        for (;;) {
            unsigned v;
            asm volatile("ld.global.cg.u32 %0, [%1];" : "=r"(v) : "l"(&g_bar));
            if (v - rb >= need) break;
            __nanosleep(64);
        }
    }
    __syncthreads();
}

// ---------------------------------------------------------------------------
// 64x64x256 FFMA2 tile GEMM, BK=32, per-128-thread-half (named barrier).
// mode 0: C = acc. mode 1 (DIAG): C = acc + c0*I + c1*A.
// mode 2 (ZEMIT): emit fp16(acc * 2^-6) A-tiles into g_ZH (swizzled).
// ---------------------------------------------------------------------------
__device__ __noinline__ void mm64(
    float (*As)[68], float (*Bs)[64], int barid, int tidh,
    const float* A, const float* B, float* C,
    int bM, int bN, int mode, float c0, float c1, int zmt, int rowhalf)
{
    const int tx = tidh & 15, ty = tidh >> 4;

    unsigned long long acc[8][2];
#pragma unroll
    for (int i = 0; i < 8; ++i) { acc[i][0] = 0ull; acc[i][1] = 0ull; }

    const int a_r = tidh >> 1, a_k = (tidh & 1) * 16;
    const int b_k = tidh >> 2, n0  = (tidh & 3) * 16;

    const float* Ap = A + (size_t)(bM * 64 + a_r) * D + a_k;
    const float* Bp = B + (size_t)b_k * D + bN * 64 + n0;

    float4 pa[4], pb[4];
#pragma unroll
    for (int j = 0; j < 4; ++j) {
        pa[j] = __ldcg((const float4*)(Ap + j * 4));
        pb[j] = __ldcg((const float4*)(Bp + j * 4));
    }

    for (int kt = 0; kt < 8; ++kt) {
#pragma unroll
        for (int j = 0; j < 4; ++j) {
            As[a_k + j * 4 + 0][a_r] = pa[j].x;
            As[a_k + j * 4 + 1][a_r] = pa[j].y;
            As[a_k + j * 4 + 2][a_r] = pa[j].z;
            As[a_k + j * 4 + 3][a_r] = pa[j].w;
            *(float4*)&Bs[b_k][n0 + j * 4] = pb[j];
        }
        BARH(barid);

        if (kt < 7) {
#pragma unroll
            for (int j = 0; j < 4; ++j) {
                pa[j] = __ldcg((const float4*)(Ap + (kt + 1) * 32 + j * 4));
                pb[j] = __ldcg((const float4*)(Bp + (size_t)(kt + 1) * 32 * D + j * 4));
            }
        }

#pragma unroll
        for (int kk = 0; kk < 32; ++kk) {
            float4 a0 = *(const float4*)&As[kk][ty * 8];
            float4 a1 = *(const float4*)&As[kk][ty * 8 + 4];
            ulonglong2 bq = *(const ulonglong2*)&Bs[kk][tx * 4];
            float a[8] = {a0.x, a0.y, a0.z, a0.w, a1.x, a1.y, a1.z, a1.w};
#pragma unroll
            for (int i = 0; i < 8; ++i) {
                unsigned long long aa = dup2(a[i]);
                fma2(acc[i][0], aa, bq.x);
                fma2(acc[i][1], aa, bq.y);
            }
        }
        BARH(barid);
    }

#pragma unroll
    for (int i = 0; i < 8; ++i) {
        int row = bM * 64 + ty * 8 + i;
        int col = bN * 64 + tx * 4;
        union { ulonglong2 u; float f[4]; } v;
        v.u.x = acc[i][0]; v.u.y = acc[i][1];
        if (mode == 0) {
            *(ulonglong2*)(C + (size_t)row * D + col) = v.u;
        } else if (mode == 1) {
#pragma unroll
            for (int q = 0; q < 4; ++q) {
                float e = v.f[q] + c1 * __ldcg(g_A + (size_t)row * D + col + q);
                if (row == col + q) e += c0;
                v.f[q] = e;
            }
            *(ulonglong2*)(C + (size_t)row * D + col) = v.u;
        } else {  // ZEMIT
            __half h0 = __float2half(v.f[0] * 0.015625f);
            __half h1 = __float2half(v.f[1] * 0.015625f);
            __half h2 = __float2half(v.f[2] * 0.015625f);
            __half h3 = __float2half(v.f[3] * 0.015625f);
            int rowloc = rowhalf * 64 + ty * 8 + i;
            int g = tx >> 1;
            int du = rowloc * 8 + (g ^ (rowloc & 7));
            uint2* p = (uint2*)((char*)(g_ZH + (size_t)(zmt * 4 + bN) * 1024 + du)
                                + (tx & 1) * 8);
            *p = make_uint2(packh2(h0, h1), packh2(h2, h3));
        }
    }
}

// convB: power p, kchunk c -> fp16(P^p[k][n] * 2^-2) transposed+swizzled
__device__ __forceinline__ void convB_job(int tidh, int p, int c) {
    for (int w = tidh; w < 2048; w += 128) {
        int n = w & 255, g = w >> 8;
        const float* src = g_P + (size_t)p * MAT + (size_t)(c * 64 + g * 8) * D + n;
        __half h[8];
#pragma unroll
        for (int e = 0; e < 8; ++e)
            h[e] = __float2half(__ldcg(src + (size_t)e * D) * 0.25f);
        uint4 H;
        H.x = packh2(h[0], h[1]); H.y = packh2(h[2], h[3]);
        H.z = packh2(h[4], h[5]); H.w = packh2(h[6], h[7]);
        g_PB[(size_t)((p - 1) * 4 + c) * 2048 + n * 8 + (g ^ (n & 7))] = H;
    }
}

// z0 conv: mtile, kchunk -> fp16(z0 * 2^-6) tiles
__device__ __forceinline__ void convZ0_job(int tidh, const float* z0, int mtile, int c) {
    for (int w = tidh; w < 1024; w += 128) {
        int row = w >> 3, g = w & 7;
        const float* src = z0 + (size_t)(mtile * 128 + row) * D + c * 64 + g * 8;
        __half h[8];
#pragma unroll
        for (int e = 0; e < 8; ++e) h[e] = __float2half(src[e] * 0.015625f);
        uint4 H;
        H.x = packh2(h[0], h[1]); H.y = packh2(h[2], h[3]);
        H.z = packh2(h[4], h[5]); H.w = packh2(h[6], h[7]);
        g_ZH[(size_t)(mtile * 4 + c) * 1024 + row * 8 + (g ^ (row & 7))] = H;
    }
}

// ---------------------------------------------------------------------------
// Mega kernel: persistent preamble (2 x 128-thread halves per CTA) + fill.
// smem: preamble 2 x 17KB halves; fill A-resident 64KB + B 2x16KB = 96KB.
// ---------------------------------------------------------------------------
#define MEGA_SMEM 98304

__global__ __launch_bounds__(256, 2)
void mega_kernel(const float* __restrict__ z0, const float* __restrict__ kern,
                 float* __restrict__ out) {
    extern __shared__ __align__(128) char sm[];
    const int tid = threadIdx.x;
    const int cta = blockIdx.x;
    const int half = tid >> 7, tidh = tid & 127;
    const int hid = cta * 2 + half;               // 0..591, preamble job stride 592
    const int barid = 1 + half;
    float (*As)[68] = (float (*)[68])(sm + half * 17408);
    float (*Bs)[64] = (float (*)[64])(sm + half * 17408 + 8704);

    unsigned rb = 0; int bk = 0;                  // barrier state (tid 0 only)

    // ---- stage 0: A = kern*DT ; D1 = I/24 + A/120 -> g_T2 ----
    {
        int idx = cta * 256 + tid;                // 296*256 = 75776 threads
        if (idx < MAT) {
            float a = kern[idx] * 0.01f;
            g_A[idx] = a;
            int r = idx >> 8, c = idx & 255;
            g_T2[idx] = (r == c ? (1.f / 24.f) : 0.f) + a * (1.f / 120.f);
        }
    }
    gbar(rb, bk);

    // ---- A2 = A*A -> X0 ----
    for (int j = hid; j < 16; j += 592)
        mm64(As, Bs, barid, tidh, g_A, g_A, g_X, j >> 2, j & 3, 0, 0.f, 0.f, 0, 0);
    gbar(rb, bk);

    // ---- D2 = A2*D1 + I/2 + A/6 -> g_T1 ----
    for (int j = hid; j < 16; j += 592)
        mm64(As, Bs, barid, tidh, g_X, g_T2, g_T1, j >> 2, j & 3, 1, 0.5f, 1.f / 6.f, 0, 0);
    gbar(rb, bk);

    // ---- E = A2*D2 + I + A -> g_P[1] ----
    for (int j = hid; j < 16; j += 592)
        mm64(As, Bs, barid, tidh, g_X, g_T1, g_P + MAT, j >> 2, j & 3, 1, 1.f, 1.f, 0, 0);
    gbar(rb, bk);

    // ---- doubling s=0..6: P[m+i] = P[m]*P[i]; convB of powers (m/2, m] ----
    for (int s = 0; s < 7; ++s) {
        int m = 1 << s;
        int nmm = 16 * m;
        int ncv = (s == 0) ? 4 : 2 * m;
        for (int j = hid; j < nmm + ncv; j += 592) {
            if (j < nmm) {
                int i = 1 + (j >> 4), t = j & 15;
                mm64(As, Bs, barid, tidh, g_P + (size_t)m * MAT, g_P + (size_t)i * MAT,
                     g_P + (size_t)(m + i) * MAT, t >> 2, t & 3, 0, 0.f, 0.f, 0, 0);
            } else {
                int e = j - nmm;
                int p = (s == 0) ? 1 : (m / 2 + 1 + (e >> 2));
                convB_job(tidh, p, e & 3);
            }
        }
        gbar(rb, bk);
    }

    // ---- P256 -> g_T2 ; + convB of powers 65..128 ----
    for (int j = hid; j < 16 + 256; j += 592) {
        if (j < 16)
            mm64(As, Bs, barid, tidh, g_P + (size_t)128 * MAT, g_P + (size_t)128 * MAT,
                 g_T2, j >> 2, j & 3, 0, 0.f, 0.f, 0, 0);
        else { int e = j - 16; convB_job(tidh, 65 + (e >> 2), e & 3); }
    }
    gbar(rb, bk);

    // ---- P512 = P256*P256 -> g_T1 ----
    for (int j = hid; j < 16; j += 592)
        mm64(As, Bs, barid, tidh, g_T2, g_T2, g_T1, j >> 2, j & 3, 0, 0.f, 0.f, 0, 0);
    gbar(rb, bk);

    // ---- Q1: E^384 -> X1 ; E^640 -> X2 ; E^768 -> X3 ----
    for (int j = hid; j < 48; j += 592) {
        int q = j >> 4, t = j & 15;
        const float* Aq = (q == 2) ? g_T2 : g_P + (size_t)128 * MAT;
        const float* Bq = (q == 0) ? g_T2 : g_T1;
        mm64(As, Bs, barid, tidh, Aq, Bq, g_X + (size_t)(q + 1) * MAT,
             t >> 2, t & 3, 0, 0.f, 0.f, 0, 0);
    }
    gbar(rb, bk);

    // ---- Q2: E^896 = E^384 * P512 -> X0 ----
    for (int j = hid; j < 16; j += 592)
        mm64(As, Bs, barid, tidh, g_X + MAT, g_T1, g_X, j >> 2, j & 3, 0, 0.f, 0.f, 0, 0);
    gbar(rb, bk);

    // ---- Z stage: Z_j = z0*Q_j (ZEMIT fp16) + z0's own tiles ----
    for (int j = hid; j < 480; j += 592) {
        if (j < 448) {
            int zj = 1 + (j >> 6), t = j & 63;
            int bM = t >> 2, bN = t & 3;
            const float* Q =
                (zj == 1) ? g_P + (size_t)128 * MAT :
                (zj == 2) ? g_T2 :
                (zj == 3) ? g_X + (size_t)1 * MAT :
                (zj == 4) ? g_T1 :
                (zj == 5) ? g_X + (size_t)2 * MAT :
                (zj == 6) ? g_X + (size_t)3 * MAT : g_X;
            mm64(As, Bs, barid, tidh, z0, Q, nullptr, bM, bN, 2, 0.f, 0.f,
                 zj * 8 + (bM >> 1), bM & 1);
        } else {
            int e = j - 448;
            convZ0_job(tidh, z0, e >> 2, e & 3);
        }
    }
    gbar(rb, bk);   // barrier 16: preamble results visible (L2), fill reads via cp.async.cg

    // ======================= FILL phase =======================
    const uint32_t sbase = smem_u32(sm);
    const int wid = tid >> 5, lid = tid & 31;
    const int warp_m = wid >> 2, warp_n = wid & 3;
    const int lq = lid >> 3, lr = lid & 7;
    const uint32_t a_row = warp_m * 64 + (lq & 1) * 8 + lr;
    const uint32_t b_row = warp_n * 32 + (lq & 1) * 8 + lr;
    const int gh = lq >> 1;

    __shared__ unsigned s_job;
    unsigned trb = 0; bool tinit = false;

    for (;;) {
        // dynamic ticket (reset-free; run adds exactly NJOBS+NCTA pulls)
        __syncthreads();
        if (tid == 0) {
            unsigned v = atomicAdd(&g_tick, 1u);
            if (!tinit) { trb = v - (v % (unsigned)TICKS_PER_RUN); tinit = true; }
            s_job = v - trb;
        }
        __syncthreads();
        unsigned job = s_job;
        if (job >= NJOBS) break;

        const int zg   = (int)(job >> 7);         // 0..15 (z-major: B shared in L2)
        const int tile = (int)(job & 127);
        const int tile_m = tile >> 1, tile_n = tile & 1;

        // A tile resident: 4 chunks x 16KB at smem [0, 64K)
        {
            const char* a0 = (const char*)(g_ZH + (size_t)tile_m * 4096);
#pragma unroll
            for (int c = 0; c < 4; ++c)
#pragma unroll
                for (int q = 0; q < 4; ++q)
                    CP16(sbase + c * 16384 + tid * 16 + q * 4096,
                         a0 + c * 16384 + tid * 16 + q * 4096);
        }
        // B chunk 0
        {
            const char* b0 = (const char*)(g_PB + (size_t)(zg * 8 * 4) * 2048
                                           + tile_n * 1024);
#pragma unroll
            for (int q = 0; q < 4; ++q)
                CP16(sbase + 65536 + tid * 16 + q * 4096, b0 + tid * 16 + q * 4096);
        }
        CP_COMMIT();

        float acc[4][4][4];

        for (int idx = 0; idx < 32; ++idx) {
            if (idx + 1 < 32) {
                int z = zg * 8 + ((idx + 1) >> 2), c = (idx + 1) & 3;
                const char* b0 = (const char*)(g_PB + (size_t)(z * 4 + c) * 2048
                                               + tile_n * 1024);
                uint32_t dst = sbase + 65536 + ((idx + 1) & 1) * 16384 + tid * 16;
#pragma unroll
                for (int q = 0; q < 4; ++q)
                    CP16(dst + q * 4096, b0 + tid * 16 + q * 4096);
                CP_COMMIT();
                CP_WAIT1();
            } else {
                CP_WAIT0();
            }
            __syncthreads();

            const int c = idx & 3;
            if (c == 0) {
#pragma unroll
                for (int i = 0; i < 4; ++i)
#pragma unroll
                    for (int j = 0; j < 4; ++j)
#pragma unroll
                        for (int q = 0; q < 4; ++q) acc[i][j][q] = 0.f;
            }

            const uint32_t ab  = sbase + c * 16384;
            const uint32_t bhb = sbase + 65536 + (idx & 1) * 16384;
#pragma unroll
            for (int ks = 0; ks < 4; ++ks) {
                const uint32_t gx = ((uint32_t)(ks * 2 + gh) ^ lr) * 16;
                uint32_t ah[4][4], bh[2][4];
#pragma unroll
                for (int mf = 0; mf < 4; ++mf)
                    ldsm4(ah[mf], ab + (a_row + mf * 16) * 128 + gx);
#pragma unroll
                for (int nf = 0; nf < 2; ++nf)
                    ldsm4(bh[nf], bhb + (b_row + nf * 16) * 128 + gx);
#pragma unroll
                for (int mf = 0; mf < 4; ++mf)
#pragma unroll
                    for (int j = 0; j < 4; ++j) {
                        const int n2 = j >> 1, e = j & 1;
                        mma16816h(acc[mf][j], ah[mf], bh[n2][e], bh[n2][e + 2]);
                    }
            }

            if (c == 3) {   // epilogue for z (undo 2^-8 operand scaling)
                const int z = zg * 8 + (idx >> 2);
                const int t  = (tile_m >> 3) * CHUNK + z;
                const int b0r = (tile_m & 7) * 128 + warp_m * 64;
                const int nb = tile_n * 128 + warp_n * 32 + (lid & 3) * 2;
                const int rr = lid >> 2;
#pragma unroll
                for (int mf = 0; mf < 4; ++mf)
#pragma unroll
                    for (int j = 0; j < 4; ++j) {
                        int b = b0r + mf * 16 + rr;
                        float* p0 = out + ((size_t)b * TSTEPS + t) * D + nb + j * 8;
                        float* p1 = out + ((size_t)(b + 8) * TSTEPS + t) * D + nb + j * 8;
                        *(float2*)p0 = make_float2(acc[mf][j][0] * 256.f,
                                                   acc[mf][j][1] * 256.f);
                        *(float2*)p1 = make_float2(acc[mf][j][2] * 256.f,
                                                   acc[mf][j][3] * 256.f);
                    }
            }
            __syncthreads();
        }
    }
}

// ---------------------------------------------------------------------------
// Launch: single persistent kernel
// ---------------------------------------------------------------------------
extern "C" void kernel_launch(void* const* d_in, const int* in_sizes, int n_in,
                              void* d_out, int out_size) {
    const float* z0   = (const float*)d_in[0];
    const float* kern = (const float*)d_in[1];
    float* out = (float*)d_out;
    (void)in_sizes; (void)n_in; (void)out_size;

    cudaFuncSetAttribute(mega_kernel,
                         cudaFuncAttributeMaxDynamicSharedMemorySize, MEGA_SMEM);
    mega_kernel<<<NCTA, 256, MEGA_SMEM>>>(z0, kern, out);
}

// round 16
// speedup vs baseline: 1.1446x; 1.1446x over previous
#include <cuda_runtime.h>
#include <cuda_fp16.h>
#include <cstdint>

// Problem constants
#define D       256
#define BATCH   1024
#define TSTEPS  1024
#define CHUNK   128
#define MAT     (D * D)
#define NCTA    512                // persistent preamble grid (guaranteed resident)

// ---------------------------------------------------------------------------
// Static device scratch
// ---------------------------------------------------------------------------
__device__ float g_A [MAT];                   // A = kernel * DT
__device__ float g_T1[MAT];                   // D2, later P512
__device__ float g_T2[MAT];                   // D1, later P256
__device__ float g_X [4 * MAT];               // A2/E^896, E^384, E^640, E^768
__device__ float g_P [(CHUNK + 1) * MAT];     // P[i] = E^i fp32, i=1..128
__device__ unsigned g_bar;                    // global barrier counter (reset by fill)
// fp16 operands, pre-tiled + pre-swizzled (XOR-8 on 16B groups) for ldmatrix:
__device__ uint4 g_PB[128 * 4 * 2048];        // B^T tiles (hi only), 16 MB
__device__ uint4 g_ZH[64 * 4 * 1024];         // A tiles (hi only), 4 MB

// ---------------------------------------------------------------------------
// Helpers
// ---------------------------------------------------------------------------
__device__ __forceinline__ uint32_t smem_u32(const void* p) {
    uint32_t a;
    asm("{ .reg .u64 t; cvta.to.shared.u64 t, %1; cvt.u32.u64 %0, t; }"
        : "=r"(a) : "l"(p));
    return a;
}
__device__ __forceinline__ void fma2(unsigned long long& d,
                                     unsigned long long a,
                                     unsigned long long b) {
    asm("fma.rn.f32x2 %0, %1, %2, %0;" : "+l"(d) : "l"(a), "l"(b));
}
__device__ __forceinline__ unsigned long long dup2(float x) {
    unsigned long long r;
    asm("mov.b64 %0, {%1, %1};" : "=l"(r) : "f"(x));
    return r;
}
__device__ __forceinline__ void ldsm4(uint32_t* r, uint32_t addr) {
    asm volatile("ldmatrix.sync.aligned.m8n8.x4.shared.b16 {%0,%1,%2,%3}, [%4];"
                 : "=r"(r[0]), "=r"(r[1]), "=r"(r[2]), "=r"(r[3]) : "r"(addr));
}
__device__ __forceinline__ void mma16816h(float* d, const uint32_t* a,
                                          uint32_t b0, uint32_t b1) {
    asm volatile(
        "mma.sync.aligned.m16n8k16.row.col.f32.f16.f16.f32 "
        "{%0,%1,%2,%3}, {%4,%5,%6,%7}, {%8,%9}, {%0,%1,%2,%3};"
        : "+f"(d[0]), "+f"(d[1]), "+f"(d[2]), "+f"(d[3])
        : "r"(a[0]), "r"(a[1]), "r"(a[2]), "r"(a[3]), "r"(b0), "r"(b1));
}
#define CP16(dst, src) \
    asm volatile("cp.async.cg.shared.global [%0], [%1], 16;" \
                 :: "r"(dst), "l"(src))
#define CP_COMMIT() asm volatile("cp.async.commit_group;" ::: "memory")
#define CP_WAIT1()  asm volatile("cp.async.wait_group 1;" ::: "memory")
#define CP_WAIT0()  asm volatile("cp.async.wait_group 0;" ::: "memory")

__device__ __forceinline__ uint32_t packh2(__half a, __half b) {
    __half_raw ar = *(__half_raw*)&a, br = *(__half_raw*)&b;
    return (uint32_t)ar.x | ((uint32_t)br.x << 16);
}

// Global barrier (monotonic counter; reset to 0 by fill_kernel each run).
__device__ __forceinline__ void gbar(unsigned& target) {
    __syncthreads();
    target += NCTA;
    if (threadIdx.x == 0) {
        __threadfence();
        atomicAdd(&g_bar, 1u);
        unsigned v;
        for (;;) {
            asm volatile("ld.global.cg.u32 %0, [%1];" : "=r"(v) : "l"(&g_bar));
            if (v >= target) break;
            __nanosleep(64);
        }
    }
    __syncthreads();
}

// ---------------------------------------------------------------------------
// 64x64x256 FFMA2 tile GEMM, BK=32 (8 iterations). .cg global loads for
// coherence across barriers. 128 threads, 8x4 microtile.
// mode 0: C = acc. mode 1 (DIAG): C = acc + c0*I + c1*A (elementwise).
// mode 2 (ZEMIT): no C; emit fp16(acc * 2^-6) A-tiles into g_ZH (swizzled).
// ---------------------------------------------------------------------------
__device__ __noinline__ void mm64(
    float (*As)[68], float (*Bs)[64],
    const float* A, const float* B, float* C,
    int bM, int bN, int mode, float c0, float c1, int zmt, int rowhalf)
{
    const int tid = threadIdx.x;
    const int tx = tid & 15, ty = tid >> 4;

    unsigned long long acc[8][2];
#pragma unroll
    for (int i = 0; i < 8; ++i) { acc[i][0] = 0ull; acc[i][1] = 0ull; }

    const int a_r = tid >> 1, a_k = (tid & 1) * 16;
    const int b_k = tid >> 2, n0  = (tid & 3) * 16;

    const float* Ap = A + (size_t)(bM * 64 + a_r) * D + a_k;
    const float* Bp = B + (size_t)b_k * D + bN * 64 + n0;

    float4 pa[4], pb[4];
#pragma unroll
    for (int j = 0; j < 4; ++j) {
        pa[j] = __ldcg((const float4*)(Ap + j * 4));
        pb[j] = __ldcg((const float4*)(Bp + j * 4));
    }

    for (int kt = 0; kt < 8; ++kt) {
#pragma unroll
        for (int j = 0; j < 4; ++j) {
            As[a_k + j * 4 + 0][a_r] = pa[j].x;
            As[a_k + j * 4 + 1][a_r] = pa[j].y;
            As[a_k + j * 4 + 2][a_r] = pa[j].z;
            As[a_k + j * 4 + 3][a_r] = pa[j].w;
            *(float4*)&Bs[b_k][n0 + j * 4] = pb[j];
        }
        __syncthreads();

        if (kt < 7) {
#pragma unroll
            for (int j = 0; j < 4; ++j) {
                pa[j] = __ldcg((const float4*)(Ap + (kt + 1) * 32 + j * 4));
                pb[j] = __ldcg((const float4*)(Bp + (size_t)(kt + 1) * 32 * D + j * 4));
            }
        }

#pragma unroll
        for (int kk = 0; kk < 32; ++kk) {
            float4 a0 = *(const float4*)&As[kk][ty * 8];
            float4 a1 = *(const float4*)&As[kk][ty * 8 + 4];
            ulonglong2 bq = *(const ulonglong2*)&Bs[kk][tx * 4];
            float a[8] = {a0.x, a0.y, a0.z, a0.w, a1.x, a1.y, a1.z, a1.w};
#pragma unroll
            for (int i = 0; i < 8; ++i) {
                unsigned long long aa = dup2(a[i]);
                fma2(acc[i][0], aa, bq.x);
                fma2(acc[i][1], aa, bq.y);
            }
        }
        __syncthreads();
    }

#pragma unroll
    for (int i = 0; i < 8; ++i) {
        int row = bM * 64 + ty * 8 + i;
        int col = bN * 64 + tx * 4;
        union { ulonglong2 u; float f[4]; } v;
        v.u.x = acc[i][0]; v.u.y = acc[i][1];
        if (mode == 0) {
            *(ulonglong2*)(C + (size_t)row * D + col) = v.u;
        } else if (mode == 1) {
#pragma unroll
            for (int q = 0; q < 4; ++q) {
                float e = v.f[q] + c1 * __ldcg(g_A + (size_t)row * D + col + q);
                if (row == col + q) e += c0;
                v.f[q] = e;
            }
            *(ulonglong2*)(C + (size_t)row * D + col) = v.u;
        } else {  // ZEMIT: fp16(val * 2^-6) -> g_ZH
            __half h0 = __float2half(v.f[0] * 0.015625f);
            __half h1 = __float2half(v.f[1] * 0.015625f);
            __half h2 = __float2half(v.f[2] * 0.015625f);
            __half h3 = __float2half(v.f[3] * 0.015625f);
            int rowloc = rowhalf * 64 + ty * 8 + i;
            int g = tx >> 1;
            int du = rowloc * 8 + (g ^ (rowloc & 7));
            uint2* p = (uint2*)((char*)(g_ZH + (size_t)(zmt * 4 + bN) * 1024 + du)
                                + (tx & 1) * 8);
            *p = make_uint2(packh2(h0, h1), packh2(h2, h3));
        }
    }
}

// convB job: power p, kchunk c -> fp16(P^p[k][n] * 2^-2) transposed+swizzled
__device__ __forceinline__ void convB_job(int p, int c) {
    for (int w = threadIdx.x; w < 2048; w += 128) {
        int n = w & 255, g = w >> 8;
        const float* src = g_P + (size_t)p * MAT + (size_t)(c * 64 + g * 8) * D + n;
        __half h[8];
#pragma unroll
        for (int e = 0; e < 8; ++e)
            h[e] = __float2half(__ldcg(src + (size_t)e * D) * 0.25f);
        uint4 H;
        H.x = packh2(h[0], h[1]); H.y = packh2(h[2], h[3]);
        H.z = packh2(h[4], h[5]); H.w = packh2(h[6], h[7]);
        g_PB[(size_t)((p - 1) * 4 + c) * 2048 + n * 8 + (g ^ (n & 7))] = H;
    }
}

// z0 conv job: mtile (0..7), kchunk c -> fp16(z0 * 2^-6) tiles
__device__ __forceinline__ void convZ0_job(const float* z0, int mtile, int c) {
    for (int w = threadIdx.x; w < 1024; w += 128) {
        int row = w >> 3, g = w & 7;
        const float* src = z0 + (size_t)(mtile * 128 + row) * D + c * 64 + g * 8;
        __half h[8];
#pragma unroll
        for (int e = 0; e < 8; ++e) h[e] = __float2half(src[e] * 0.015625f);
        uint4 H;
        H.x = packh2(h[0], h[1]); H.y = packh2(h[2], h[3]);
        H.z = packh2(h[4], h[5]); H.w = packh2(h[6], h[7]);
        g_ZH[(size_t)(mtile * 4 + c) * 1024 + row * 8 + (g ^ (row & 7))] = H;
    }
}

// ---------------------------------------------------------------------------
// Persistent preamble (unchanged from R14 known-good): prep -> Horner-expm(3)
// -> doubling(7, convB overlapped) -> P256(+convB tail) -> P512 -> Q1 -> Q2
// -> Z(ZEMIT)+z0conv. 15 barriers.
// ---------------------------------------------------------------------------
__global__ __launch_bounds__(128, 4)
void preamble_kernel(const float* __restrict__ z0, const float* __restrict__ kern) {
    __shared__ float As[32][68];
    __shared__ float Bs[32][64];
    const int cta = blockIdx.x;
    const int tid = threadIdx.x;
    unsigned target = 0;

    // stage 0: A = kern*DT ; D1 = I/24 + A/120 -> g_T2   (65536 thr = MAT)
    {
        int idx = cta * 128 + tid;
        float a = kern[idx] * 0.01f;
        g_A[idx] = a;
        int r = idx >> 8, c = idx & 255;
        g_T2[idx] = (r == c ? (1.f / 24.f) : 0.f) + a * (1.f / 120.f);
    }
    gbar(target);

    // stage 1: A2 = A*A -> g_X[0]
    for (int j = cta; j < 16; j += NCTA)
        mm64(As, Bs, g_A, g_A, g_X, j >> 2, j & 3, 0, 0.f, 0.f, 0, 0);
    gbar(target);

    // stage 2: D2 = A2*D1 + I/2 + A/6 -> g_T1
    for (int j = cta; j < 16; j += NCTA)
        mm64(As, Bs, g_X, g_T2, g_T1, j >> 2, j & 3, 1, 0.5f, 1.f / 6.f, 0, 0);
    gbar(target);

    // stage 3: E = A2*D2 + I + A -> g_P[1]
    for (int j = cta; j < 16; j += NCTA)
        mm64(As, Bs, g_X, g_T1, g_P + MAT, j >> 2, j & 3, 1, 1.f, 1.f, 0, 0);
    gbar(target);

    // doubling s=0..6 (m=2^s): P[m+i] = P[m]*P[i]; convB of powers (m/2, m]
    for (int s = 0; s < 7; ++s) {
        int m = 1 << s;
        int nmm = 16 * m;
        int ncv = (s == 0) ? 4 : 2 * m;
        for (int j = cta; j < nmm + ncv; j += NCTA) {
            if (j < nmm) {
                int i = 1 + (j >> 4), t = j & 15;
                mm64(As, Bs, g_P + (size_t)m * MAT, g_P + (size_t)i * MAT,
                     g_P + (size_t)(m + i) * MAT, t >> 2, t & 3, 0, 0.f, 0.f, 0, 0);
            } else {
                int e = j - nmm;
                int p = (s == 0) ? 1 : (m / 2 + 1 + (e >> 2));
                convB_job(p, e & 3);
            }
        }
        gbar(target);
    }

    // P256 = P128*P128 -> g_T2 (D1 dead)  + convB of powers 65..128
    for (int j = cta; j < 16 + 256; j += NCTA) {
        if (j < 16)
            mm64(As, Bs, g_P + (size_t)128 * MAT, g_P + (size_t)128 * MAT, g_T2,
                 j >> 2, j & 3, 0, 0.f, 0.f, 0, 0);
        else { int e = j - 16; convB_job(65 + (e >> 2), e & 3); }
    }
    gbar(target);

    // P512 = P256*P256 -> g_T1 (D2 dead)
    for (int j = cta; j < 16; j += NCTA)
        mm64(As, Bs, g_T2, g_T2, g_T1, j >> 2, j & 3, 0, 0.f, 0.f, 0, 0);
    gbar(target);

    // Q1: E^384 = P128*P256 -> X1 ; E^640 = P128*P512 -> X2 ; E^768 = P256*P512 -> X3
    for (int j = cta; j < 48; j += NCTA) {
        int q = j >> 4, t = j & 15;
        const float* Aq = (q == 2) ? g_T2 : g_P + (size_t)128 * MAT;
        const float* Bq = (q == 0) ? g_T2 : g_T1;
        mm64(As, Bs, Aq, Bq, g_X + (size_t)(q + 1) * MAT, t >> 2, t & 3, 0, 0.f, 0.f, 0, 0);
    }
    gbar(target);

    // Q2: E^896 = E^384 * P512 -> X0 (A2 dead)
    for (int j = cta; j < 16; j += NCTA)
        mm64(As, Bs, g_X + MAT, g_T1, g_X, j >> 2, j & 3, 0, 0.f, 0.f, 0, 0);
    gbar(target);

    // Z stage: Z_j = z0 * Q_j (j=1..7), fp16 emitted directly; + z0's own tiles.
    for (int j = cta; j < 480; j += NCTA) {
        if (j < 448) {
            int zj = 1 + (j >> 6), t = j & 63;
            int bM = t >> 2, bN = t & 3;
            const float* Q =
                (zj == 1) ? g_P + (size_t)128 * MAT :
                (zj == 2) ? g_T2 :
                (zj == 3) ? g_X + (size_t)1 * MAT :
                (zj == 4) ? g_T1 :
                (zj == 5) ? g_X + (size_t)2 * MAT :
                (zj == 6) ? g_X + (size_t)3 * MAT : g_X;
            mm64(As, Bs, z0, Q, nullptr, bM, bN, 2, 0.f, 0.f,
                 zj * 8 + (bM >> 1), bM & 1);
        } else {
            int e = j - 448;
            convZ0_job(z0, e >> 2, e & 3);
        }
    }
    // no final barrier: kernel boundary orders vs fill; g_bar reset by fill.
}

// ---------------------------------------------------------------------------
// HMMA fill v2: A-resident 4-z jobs. grid 4096 = 32 zgroups x 128 tiles
// (zg-major: concurrent CTAs share B slices in L2). 256 threads, 2 CTAs/SM.
// smem 96KB = A resident 64KB (4 k-chunks) + B double buffer 2x16KB.
// Per job: 16 chunk-iterations; epilogue per z (every 4th chunk).
// ---------------------------------------------------------------------------
#define FILL_SMEM 98304

__global__ __launch_bounds__(256, 2)
void fill_kernel(float* __restrict__ out) {
    extern __shared__ __align__(128) char sm[];
    const uint32_t sbase = smem_u32(sm);
    const int tid = threadIdx.x;
    if (blockIdx.x == 0 && tid == 0) g_bar = 0;    // reset for next run's preamble
    const int zg = blockIdx.x >> 7;                // 0..31 (4 z each)
    const int tile = blockIdx.x & 127;
    const int tile_m = tile >> 1, tile_n = tile & 1;
    const int wid = tid >> 5, lid = tid & 31;
    const int warp_m = wid >> 2, warp_n = wid & 3;
    const int lq = lid >> 3, lr = lid & 7;
    const uint32_t a_row = warp_m * 64 + (lq & 1) * 8 + lr;
    const uint32_t b_row = warp_n * 32 + (lq & 1) * 8 + lr;
    const int gh = lq >> 1;

    // prologue: A resident (64KB, all 4 k-chunks) + B chunk 0 (16KB)
    {
        const char* a0 = (const char*)(g_ZH + (size_t)tile_m * 4096) + tid * 16;
#pragma unroll
        for (int q = 0; q < 16; ++q)
            CP16(sbase + tid * 16 + q * 4096, a0 + q * 4096);
        const char* b0 = (const char*)(g_PB + (size_t)(zg * 4) * 4 * 2048
                                       + tile_n * 1024) + tid * 16;
#pragma unroll
        for (int q = 0; q < 4; ++q)
            CP16(sbase + 65536 + tid * 16 + q * 4096, b0 + q * 4096);
        CP_COMMIT();
    }

    float acc[4][4][4];

    for (int idx = 0; idx < 16; ++idx) {
        if (idx + 1 < 16) {   // prefetch next B chunk
            int z = zg * 4 + ((idx + 1) >> 2), c = (idx + 1) & 3;
            const char* b0 = (const char*)(g_PB + (size_t)(z * 4 + c) * 2048
                                           + tile_n * 1024) + tid * 16;
            uint32_t dst = sbase + 65536 + ((idx + 1) & 1) * 16384 + tid * 16;
#pragma unroll
            for (int q = 0; q < 4; ++q)
                CP16(dst + q * 4096, b0 + q * 4096);
            CP_COMMIT();
            CP_WAIT1();
        } else {
            CP_WAIT0();
        }
        __syncthreads();

        const int c = idx & 3;
        if (c == 0) {
#pragma unroll
            for (int i = 0; i < 4; ++i)
#pragma unroll
                for (int j = 0; j < 4; ++j)
#pragma unroll
                    for (int q = 0; q < 4; ++q) acc[i][j][q] = 0.f;
        }

        const uint32_t ab  = sbase + c * 16384;                 // A chunk (resident)
        const uint32_t bhb = sbase + 65536 + (idx & 1) * 16384; // B buffer
#pragma unroll
        for (int ks = 0; ks < 4; ++ks) {
            const uint32_t gx = ((uint32_t)(ks * 2 + gh) ^ lr) * 16;
            uint32_t ah[4][4], bh[2][4];
#pragma unroll
            for (int mf = 0; mf < 4; ++mf)
                ldsm4(ah[mf], ab + (a_row + mf * 16) * 128 + gx);
#pragma unroll
            for (int nf = 0; nf < 2; ++nf)
                ldsm4(bh[nf], bhb + (b_row + nf * 16) * 128 + gx);
#pragma unroll
            for (int mf = 0; mf < 4; ++mf)
#pragma unroll
                for (int j = 0; j < 4; ++j) {
                    const int n2 = j >> 1, e = j & 1;
                    mma16816h(acc[mf][j], ah[mf], bh[n2][e], bh[n2][e + 2]);
                }
        }

        if (c == 3) {   // epilogue for this z (undo 2^-8 operand scaling)
            const int z = zg * 4 + (idx >> 2);
            const int t  = (tile_m >> 3) * CHUNK + z;
            const int b0r = (tile_m & 7) * 128 + warp_m * 64;
            const int nb = tile_n * 128 + warp_n * 32 + (lid & 3) * 2;
            const int rr = lid >> 2;
#pragma unroll
            for (int mf = 0; mf < 4; ++mf)
#pragma unroll
                for (int j = 0; j < 4; ++j) {
                    int b = b0r + mf * 16 + rr;
                    float* p0 = out + ((size_t)b * TSTEPS + t) * D + nb + j * 8;
                    float* p1 = out + ((size_t)(b + 8) * TSTEPS + t) * D + nb + j * 8;
                    *(float2*)p0 = make_float2(acc[mf][j][0] * 256.f,
                                               acc[mf][j][1] * 256.f);
                    *(float2*)p1 = make_float2(acc[mf][j][2] * 256.f,
                                               acc[mf][j][3] * 256.f);
                }
        }
        __syncthreads();   // load-bearing: protects B buffer reused 2 iters later
    }
}

// ---------------------------------------------------------------------------
// Launch: persistent preamble -> fill
// ---------------------------------------------------------------------------
extern "C" void kernel_launch(void* const* d_in, const int* in_sizes, int n_in,
                              void* d_out, int out_size) {
    const float* z0   = (const float*)d_in[0];
    const float* kern = (const float*)d_in[1];
    float* out = (float*)d_out;
    (void)in_sizes; (void)n_in; (void)out_size;

    preamble_kernel<<<NCTA, 128>>>(z0, kern);

    cudaFuncSetAttribute(fill_kernel,
                         cudaFuncAttributeMaxDynamicSharedMemorySize, FILL_SMEM);
    fill_kernel<<<4096, 256, FILL_SMEM>>>(out);
}